// round 15
// baseline (speedup 1.0000x reference)
#include <cuda_runtime.h>
#include <cuda_fp16.h>

#define NPTS  4096
#define NPQ   1024
#define NB    8
#define PXT   262144
#define EPSB  1e-5f
#define OUT_XYZ 24576
#define FLT_BIG 3.4e38f

typedef unsigned int   u32;
typedef unsigned short u16;

/* per-point features pf = W0[:,3:67] @ points : [b*n][64] fp32 (8 MB, L2-resident) */
__device__ float g_pf[(size_t)NB * NPTS * 64];

/* fp16 weight images */
__device__ u16 g_W1f[128 * 64];
__device__ u16 g_W2f[256 * 128];

/* stats: stats0 @0(64), stats2 @192(256) */
__device__ float g_sum[448], g_sq[448];
/* layer-1 second-moment machinery */
__device__ float g_M[64 * 64];
__device__ float g_S[64];
__device__ float g_a1[128], g_c1[128];

/* ---------- helpers ---------- */
__device__ __forceinline__ void split_pair_f16(float v0, float v1, u32& hp, u32& lp) {
    asm("cvt.rn.f16x2.f32 %0, %1, %2;" : "=r"(hp) : "f"(v1), "f"(v0));
    __half2 h2 = *reinterpret_cast<__half2*>(&hp);
    float d0 = v0 - __half2float(__low2half(h2));
    float d1 = v1 - __half2float(__high2half(h2));
    asm("cvt.rn.f16x2.f32 %0, %1, %2;" : "=r"(lp) : "f"(d1), "f"(d0));
}
__device__ __forceinline__ void f16split1(float v, u16& h, u16& l) {
    __half hh = __float2half_rn(v);
    h = *reinterpret_cast<u16*>(&hh);
    __half ll = __float2half_rn(v - __half2float(hh));
    l = *reinterpret_cast<u16*>(&ll);
}
__device__ __forceinline__ u32 smem_u32_of(const void* p) {
    u32 a;
    asm("{ .reg .u64 t; cvta.to.shared.u64 t, %1; cvt.u32.u64 %0, t; }" : "=r"(a) : "l"(p));
    return a;
}
__device__ __forceinline__ void ldsm4(u32* r, u32 addr) {
    asm volatile("ldmatrix.sync.aligned.m8n8.x4.shared.b16 {%0,%1,%2,%3}, [%4];"
        : "=r"(r[0]), "=r"(r[1]), "=r"(r[2]), "=r"(r[3]) : "r"(addr));
}
__device__ __forceinline__ void hmma16(float* d, const u32* a, u32 b0, u32 b1) {
    asm volatile("mma.sync.aligned.m16n8k16.row.col.f32.f16.f16.f32 "
        "{%0,%1,%2,%3}, {%4,%5,%6,%7}, {%8,%9}, {%0,%1,%2,%3};"
        : "+f"(d[0]), "+f"(d[1]), "+f"(d[2]), "+f"(d[3])
        : "r"(a[0]), "r"(a[1]), "r"(a[2]), "r"(a[3]), "r"(b0), "r"(b1));
}

extern __shared__ char smc[];

/* ---------- prep: zero accumulators + fp16 weight images ---------- */
__global__ void k_prep(const float* __restrict__ W1, const float* __restrict__ W2) {
    int t0 = blockIdx.x * blockDim.x + threadIdx.x;
    int nth = gridDim.x * blockDim.x;
    for (int t = t0; t < 448; t += nth) { g_sum[t] = 0.f; g_sq[t] = 0.f; }
    for (int t = t0; t < 4096; t += nth) g_M[t] = 0.f;
    for (int t = t0; t < 64; t += nth) g_S[t] = 0.f;
    for (int e = t0; e < 128 * 64; e += nth) {
        __half h = __float2half_rn(W1[e]);
        g_W1f[e] = *reinterpret_cast<u16*>(&h);
    }
    for (int e = t0; e < 256 * 128; e += nth) {
        __half h = __float2half_rn(W2[e]);
        g_W2f[e] = *reinterpret_cast<u16*>(&h);
    }
}

/* ---------- per-point features ---------- */
__global__ __launch_bounds__(256) void k_pf(const float* __restrict__ pts,
                                            const float* __restrict__ W0) {
    __shared__ float s_f[64][132];
    __shared__ float s_w[64][64];
    int tid = threadIdx.x;
    int b = blockIdx.x >> 5, n0 = (blockIdx.x & 31) * 128;

    for (int e = tid; e < 64 * 32; e += 256) {
        int c = e >> 5, nq = e & 31;
        *(float4*)&s_f[c][nq * 4] =
            *(const float4*)&pts[((size_t)(b * 64 + c)) * NPTS + n0 + nq * 4];
    }
    for (int e = tid; e < 4096; e += 256) {
        int c = e >> 6, co = e & 63;
        s_w[c][co] = W0[co * 67 + 3 + c];
    }
    __syncthreads();

    int coq = tid & 15, nq = tid >> 4;
    float acc[8][4];
#pragma unroll
    for (int i = 0; i < 8; i++)
#pragma unroll
        for (int j = 0; j < 4; j++) acc[i][j] = 0.f;

#pragma unroll 4
    for (int c = 0; c < 64; c++) {
        float4 wv = *(float4*)&s_w[c][coq * 4];
        float fv[8];
        *(float4*)&fv[0] = *(float4*)&s_f[c][nq * 8];
        *(float4*)&fv[4] = *(float4*)&s_f[c][nq * 8 + 4];
        float wj[4] = { wv.x, wv.y, wv.z, wv.w };
#pragma unroll
        for (int i = 0; i < 8; i++)
#pragma unroll
            for (int j = 0; j < 4; j++) acc[i][j] = fmaf(fv[i], wj[j], acc[i][j]);
    }
#pragma unroll
    for (int i = 0; i < 8; i++) {
        int n = n0 + nq * 8 + i;
        *(float4*)&g_pf[((size_t)b * NPTS + n) * 64 + coq * 4] =
            make_float4(acc[i][0], acc[i][1], acc[i][2], acc[i][3]);
    }
}

/* ========= layer 0 stats ONLY ========= */
__global__ __launch_bounds__(256) void k_g0s(
    const float* __restrict__ xyz, const float* __restrict__ W0,
    const int* __restrict__ smp, const int* __restrict__ nbr)
{
    __shared__ float s_R[3][64];
    __shared__ float s_sum[64], s_sq[64];
    int tid = threadIdx.x;
    int px0 = blockIdx.x * 128, b = px0 >> 15;

    if (tid < 192) {
        int k = tid >> 6, co = tid & 63;
        s_R[k][co] = W0[co * 67 + k];
    }
    if (tid < 64) { s_sum[tid] = 0.f; s_sq[tid] = 0.f; }
    __syncthreads();

    int co = tid & 63, pxq = tid >> 6;
    float rk0 = s_R[0][co], rk1 = s_R[1][co], rk2 = s_R[2][co];

    int si = smp[(px0 >> 5) + pxq];
    const float* xc = xyz + (size_t)(b * NPTS + si) * 3;
    float c0 = xc[0], c1 = xc[1], c2 = xc[2];

    float ssum = 0.f, ssq = 0.f;
#pragma unroll 4
    for (int i = 0; i < 32; i++) {
        int pxg = px0 + pxq * 32 + i;
        int ni = nbr[pxg];
        const float* xn = xyz + (size_t)(b * NPTS + ni) * 3;
        float r0 = xn[0] - c0, r1 = xn[1] - c1, r2 = xn[2] - c2;
        float pf = g_pf[((size_t)b * NPTS + ni) * 64 + co];
        float y = fmaf(rk0, r0, fmaf(rk1, r1, fmaf(rk2, r2, pf)));
        ssum += y; ssq += y * y;
    }
    atomicAdd(&s_sum[co], ssum);
    atomicAdd(&s_sq[co], ssq);
    __syncthreads();
    if (tid < 64) {
        atomicAdd(&g_sum[tid], s_sum[tid]);
        atomicAdd(&g_sq[tid], s_sq[tid]);
    }
}

/* ========= m1 v3: M = X^T X via HMMA (px = K dim), X staged ch-major =========
   8 px-tiles per block; warp (rg,cg) owns M chunk rows rg*16..+15, cols cg*32..+31,
   acc held across tiles; fp16 hi/lo 3-pass. S accumulated in per-thread regs. */
__global__ __launch_bounds__(256) void k_m1(
    const float* __restrict__ gamma, const float* __restrict__ beta,
    const float* __restrict__ W0, const float* __restrict__ xyz,
    const int* __restrict__ smp, const int* __restrict__ nbr)
{
    __shared__ u16 XH[64 * 136];   /* [ch][px] pitch 272B */
    __shared__ u16 XL[64 * 136];
    __shared__ float4 s_cf[64];
    __shared__ float s_cc[64];
    __shared__ float s_S[64];

    int tid = threadIdx.x, wid = tid >> 5, lane = tid & 31;
    if (tid < 64) {
        const float inv = 1.0f / (float)PXT;
        float mu = g_sum[tid] * inv;
        float var = g_sq[tid] * inv - mu * mu;
        float a = gamma[tid] * rsqrtf(var + EPSB);
        float4 cf;
        cf.x = a;
        cf.y = a * W0[tid * 67 + 0];
        cf.z = a * W0[tid * 67 + 1];
        cf.w = a * W0[tid * 67 + 2];
        s_cf[tid] = cf;
        s_cc[tid] = beta[tid] - a * mu;
        s_S[tid] = 0.f;
    }
    __syncthreads();

    int rg = wid >> 1, cg = wid & 1;
    u32 smb_h = smem_u32_of(XH), smb_l = smem_u32_of(XL);
    u32 arow = (u32)(rg * 16 + (lane & 15)) * 272 + ((lane >> 4) << 4);
    u32 brow = (u32)(cg * 32 + ((lane >> 4) << 3) + (lane & 7)) * 272
             + (((lane >> 3) & 1) << 4);

    int r = tid >> 1, half = tid & 1;

    float acc[4][4];
#pragma unroll
    for (int n = 0; n < 4; n++)
#pragma unroll
        for (int i = 0; i < 4; i++) acc[n][i] = 0.f;
    float4 S4[8];
#pragma unroll
    for (int j = 0; j < 8; j++) S4[j] = make_float4(0.f, 0.f, 0.f, 0.f);

    for (int t = 0; t < 8; t++) {
        int px0 = (blockIdx.x * 8 + t) * 128, b = px0 >> 15;
        {
            int px = px0 + r;
            int ni = nbr[px];
            int si = smp[px >> 5];
            const float* xn = xyz + (size_t)(b * NPTS + ni) * 3;
            const float* xc = xyz + (size_t)(b * NPTS + si) * 3;
            float r0 = xn[0] - xc[0], r1 = xn[1] - xc[1], r2 = xn[2] - xc[2];
            const float4* pf4 = (const float4*)&g_pf[((size_t)b * NPTS + ni) * 64 + half * 32];
#pragma unroll
            for (int j = 0; j < 8; j++) {
                float4 p = pf4[j];
                int k = half * 32 + j * 4;
                float4 c0 = s_cf[k], c1 = s_cf[k + 1], c2 = s_cf[k + 2], c3 = s_cf[k + 3];
                float v0 = fmaxf(fmaf(c0.x, p.x, fmaf(c0.y, r0, fmaf(c0.z, r1, fmaf(c0.w, r2, s_cc[k])))), 0.f);
                float v1 = fmaxf(fmaf(c1.x, p.y, fmaf(c1.y, r0, fmaf(c1.z, r1, fmaf(c1.w, r2, s_cc[k + 1])))), 0.f);
                float v2 = fmaxf(fmaf(c2.x, p.z, fmaf(c2.y, r0, fmaf(c2.z, r1, fmaf(c2.w, r2, s_cc[k + 2])))), 0.f);
                float v3 = fmaxf(fmaf(c3.x, p.w, fmaf(c3.y, r0, fmaf(c3.z, r1, fmaf(c3.w, r2, s_cc[k + 3])))), 0.f);
                S4[j].x += v0; S4[j].y += v1; S4[j].z += v2; S4[j].w += v3;
                u16 h, l;
                f16split1(v0, h, l); XH[k * 136 + r] = h;       XL[k * 136 + r] = l;
                f16split1(v1, h, l); XH[(k + 1) * 136 + r] = h; XL[(k + 1) * 136 + r] = l;
                f16split1(v2, h, l); XH[(k + 2) * 136 + r] = h; XL[(k + 2) * 136 + r] = l;
                f16split1(v3, h, l); XH[(k + 3) * 136 + r] = h; XL[(k + 3) * 136 + r] = l;
            }
        }
        __syncthreads();
#pragma unroll
        for (int ks = 0; ks < 8; ks++) {
            u32 ah[4], al[4], bh[2][4], bl[2][4];
            ldsm4(ah, smb_h + arow + ks * 32);
            ldsm4(al, smb_l + arow + ks * 32);
#pragma unroll
            for (int gg = 0; gg < 2; gg++) {
                ldsm4(bh[gg], smb_h + brow + (u32)gg * 16 * 272 + ks * 32);
                ldsm4(bl[gg], smb_l + brow + (u32)gg * 16 * 272 + ks * 32);
            }
#pragma unroll
            for (int pass = 0; pass < 3; pass++) {
#pragma unroll
                for (int gg = 0; gg < 2; gg++) {
#pragma unroll
                    for (int tt = 0; tt < 2; tt++) {
                        int n = gg * 2 + tt, sb = tt * 2;
                        const u32* A = (pass == 2) ? al : ah;
                        u32 B0 = (pass == 1) ? bl[gg][sb] : bh[gg][sb];
                        u32 B1 = (pass == 1) ? bl[gg][sb + 1] : bh[gg][sb + 1];
                        hmma16(acc[n], A, B0, B1);
                    }
                }
            }
        }
        __syncthreads();
    }

    /* scatter M fragments */
    {
        int mrow = rg * 16 + (lane >> 2);
#pragma unroll
        for (int n = 0; n < 4; n++) {
            int ncol = cg * 32 + n * 8 + ((lane & 3) << 1);
            atomicAdd(&g_M[mrow * 64 + ncol], acc[n][0]);
            atomicAdd(&g_M[mrow * 64 + ncol + 1], acc[n][1]);
            atomicAdd(&g_M[(mrow + 8) * 64 + ncol], acc[n][2]);
            atomicAdd(&g_M[(mrow + 8) * 64 + ncol + 1], acc[n][3]);
        }
    }
    /* S: per-thread regs -> smem -> global */
#pragma unroll
    for (int j = 0; j < 8; j++) {
        int k = half * 32 + j * 4;
        atomicAdd(&s_S[k], S4[j].x);
        atomicAdd(&s_S[k + 1], S4[j].y);
        atomicAdd(&s_S[k + 2], S4[j].z);
        atomicAdd(&s_S[k + 3], S4[j].w);
    }
    __syncthreads();
    if (tid < 64) atomicAdd(&g_S[tid], s_S[tid]);
}

/* ========= fold1: stats1 from M, S ========= */
__global__ void k_fold1(const float* __restrict__ W1,
                        const float* __restrict__ gamma,
                        const float* __restrict__ beta) {
    __shared__ float sM[4096];
    __shared__ float sWt[64 * 128];   /* [j][co] */
    int tid = threadIdx.x;            /* 128 threads */
    for (int e = tid; e < 4096; e += 128) sM[e] = g_M[e];
    for (int e = tid; e < 8192; e += 128) {
        int co = e & 127, j = e >> 7;
        sWt[j * 128 + co] = W1[co * 64 + j];
    }
    __syncthreads();
    float v = 0.f, mn = 0.f;
    for (int i = 0; i < 64; i++) {
        float wi = sWt[i * 128 + tid];
        mn = fmaf(wi, g_S[i], mn);
        float t = 0.f;
#pragma unroll 4
        for (int j = 0; j < 64; j++)
            t = fmaf(sM[i * 64 + j], sWt[j * 128 + tid], t);
        v = fmaf(wi, t, v);
    }
    const float inv = 1.0f / (float)PXT;
    float mean = mn * inv;
    float var = v * inv - mean * mean;
    float a = gamma[tid] * rsqrtf(var + EPSB);
    g_a1[tid] = a;
    g_c1[tid] = beta[tid] - a * mean;
}

/* ========= g2f: fused layer1 + layer2 ========= */
#define X0H 2304
#define X0L 20736
#define W1O 39168
#define X1H 2304
#define X1L 37120
#define W2O 71936
#define SA1 90368
#define SC1 90880
#define SCF 91392
#define SCC 92416
#define SM2F 92672

__global__ __launch_bounds__(256, 2) void k_g2f(
    const float* __restrict__ gamma0, const float* __restrict__ beta0,
    const float* __restrict__ W0, const float* __restrict__ xyz,
    const int* __restrict__ smp, const int* __restrict__ nbr,
    float* __restrict__ out)
{
    float4* s_cf = (float4*)(smc + SCF);
    float*  s_cc = (float*)(smc + SCC);
    float*  s_a1 = (float*)(smc + SA1);
    float*  s_c1 = (float*)(smc + SC1);

    int tid = threadIdx.x, wid = tid >> 5, lane = tid & 31;
    int px0 = blockIdx.x * 128, b = px0 >> 15;

    if (tid < 64) {
        const float inv = 1.0f / (float)PXT;
        float mu = g_sum[tid] * inv;
        float var = g_sq[tid] * inv - mu * mu;
        float a = gamma0[tid] * rsqrtf(var + EPSB);
        float4 cf;
        cf.x = a;
        cf.y = a * W0[tid * 67 + 0];
        cf.z = a * W0[tid * 67 + 1];
        cf.w = a * W0[tid * 67 + 2];
        s_cf[tid] = cf;
        s_cc[tid] = beta0[tid] - a * mu;
    }
    if (tid >= 128) {
        int c = tid - 128;
        s_a1[c] = g_a1[c];
        s_c1[c] = g_c1[c];
    }
    /* stage W1 (fp16) */
    for (int e = tid; e < 4096; e += 256) {
        int row = e >> 5, kp = e & 31;
        ((u32*)(smc + W1O + row * 144))[kp] = ((const u32*)g_W1f)[row * 32 + kp];
    }
    __syncthreads();
    /* stage X0: recompute x0, f16 split */
    {
        int r = tid >> 1, half = tid & 1;
        int px = px0 + r;
        int ni = nbr[px];
        int si = smp[px >> 5];
        const float* xn = xyz + (size_t)(b * NPTS + ni) * 3;
        const float* xc = xyz + (size_t)(b * NPTS + si) * 3;
        float r0 = xn[0] - xc[0], r1 = xn[1] - xc[1], r2 = xn[2] - xc[2];
        const float4* pf4 = (const float4*)&g_pf[((size_t)b * NPTS + ni) * 64 + half * 32];
        u32* xh = (u32*)(smc + X0H + r * 144 + half * 64);
        u32* xl = (u32*)(smc + X0L + r * 144 + half * 64);
#pragma unroll
        for (int j = 0; j < 8; j++) {
            float4 p = pf4[j];
            int k = half * 32 + j * 4;
            float4 c0 = s_cf[k], c1 = s_cf[k + 1], c2 = s_cf[k + 2], c3 = s_cf[k + 3];
            float v0 = fmaxf(fmaf(c0.x, p.x, fmaf(c0.y, r0, fmaf(c0.z, r1, fmaf(c0.w, r2, s_cc[k])))), 0.f);
            float v1 = fmaxf(fmaf(c1.x, p.y, fmaf(c1.y, r0, fmaf(c1.z, r1, fmaf(c1.w, r2, s_cc[k + 1])))), 0.f);
            float v2 = fmaxf(fmaf(c2.x, p.z, fmaf(c2.y, r0, fmaf(c2.z, r1, fmaf(c2.w, r2, s_cc[k + 2])))), 0.f);
            float v3 = fmaxf(fmaf(c3.x, p.w, fmaf(c3.y, r0, fmaf(c3.z, r1, fmaf(c3.w, r2, s_cc[k + 3])))), 0.f);
            split_pair_f16(v0, v1, xh[j * 2], xl[j * 2]);
            split_pair_f16(v2, v3, xh[j * 2 + 1], xl[j * 2 + 1]);
        }
    }
    __syncthreads();

    int pxg = wid >> 1, cog = wid & 1;
    u32 smb = smem_u32_of(smc);

    /* ---- GEMM1: warp tile 32px x 64co, k=64, fp16 2-pass ---- */
    {
        u32 arow1 = (u32)(pxg * 32 + (lane & 15)) * 144 + ((lane >> 4) << 4);
        u32 brow1 = (u32)(cog * 64 + ((lane >> 4) << 3) + (lane & 7)) * 144
                  + (((lane >> 3) & 1) << 4);

        float acc1[2][8][4];
#pragma unroll
        for (int m = 0; m < 2; m++)
#pragma unroll
            for (int n = 0; n < 8; n++)
#pragma unroll
                for (int i = 0; i < 4; i++) acc1[m][n][i] = 0.f;

#pragma unroll
        for (int ks = 0; ks < 4; ks++) {
            u32 ah[2][4], al[2][4], bh[4][4];
#pragma unroll
            for (int m = 0; m < 2; m++) {
                ldsm4(ah[m], smb + X0H + arow1 + (u32)m * 16 * 144 + ks * 32);
                ldsm4(al[m], smb + X0L + arow1 + (u32)m * 16 * 144 + ks * 32);
            }
#pragma unroll
            for (int gg = 0; gg < 4; gg++)
                ldsm4(bh[gg], smb + W1O + brow1 + (u32)gg * 16 * 144 + ks * 32);
#pragma unroll
            for (int pass = 0; pass < 2; pass++) {
#pragma unroll
                for (int gg = 0; gg < 4; gg++) {
#pragma unroll
                    for (int t = 0; t < 2; t++) {
                        int n = gg * 2 + t, sb = t * 2;
#pragma unroll
                        for (int m = 0; m < 2; m++) {
                            const u32* A = (pass == 1) ? al[m] : ah[m];
                            hmma16(acc1[m][n], A, bh[gg][sb], bh[gg][sb + 1]);
                        }
                    }
                }
            }
        }
        __syncthreads();   /* X0/W1 reads done; region becomes X1 */

        /* BN1+ReLU and write X1 (f16 split) into smem */
#pragma unroll
        for (int n = 0; n < 8; n++) {
            int co = cog * 64 + n * 8 + ((lane & 3) << 1);
            float a0 = s_a1[co], cc0 = s_c1[co];
            float a1v = s_a1[co + 1], cc1 = s_c1[co + 1];
#pragma unroll
            for (int m = 0; m < 2; m++) {
                int px = pxg * 32 + m * 16 + (lane >> 2);
                float v0 = fmaxf(fmaf(a0, acc1[m][n][0], cc0), 0.f);
                float v1 = fmaxf(fmaf(a1v, acc1[m][n][1], cc1), 0.f);
                float v2 = fmaxf(fmaf(a0, acc1[m][n][2], cc0), 0.f);
                float v3 = fmaxf(fmaf(a1v, acc1[m][n][3], cc1), 0.f);
                u32 hp, lp;
                split_pair_f16(v0, v1, hp, lp);
                *(u32*)(smc + X1H + px * 272 + co * 2) = hp;
                *(u32*)(smc + X1L + px * 272 + co * 2) = lp;
                split_pair_f16(v2, v3, hp, lp);
                *(u32*)(smc + X1H + (px + 8) * 272 + co * 2) = hp;
                *(u32*)(smc + X1L + (px + 8) * 272 + co * 2) = lp;
            }
        }
    }

    /* ---- GEMM2: px128 x co256 x k128, fp16 2-pass, NS-max + stats2 ---- */
    u32 arow = (u32)(pxg * 32 + (lane & 15)) * 272 + ((lane >> 4) << 4);
    u32 brow = (u32)(cog * 64 + ((lane >> 4) << 3) + (lane & 7)) * 144
             + (((lane >> 3) & 1) << 4);

    int np = blockIdx.x * 4 + pxg;
    int b2 = np >> 10, npq = np & 1023;

    for (int h = 0; h < 2; h++) {
        float acc[2][8][4];
#pragma unroll
        for (int m = 0; m < 2; m++)
#pragma unroll
            for (int n = 0; n < 8; n++)
#pragma unroll
                for (int i = 0; i < 4; i++) acc[m][n][i] = 0.f;

        for (int kc = 0; kc < 2; kc++) {
            __syncthreads();   /* X1 writes (first iter) / W2 reads done */
            for (int e = tid; e < 4096; e += 256) {
                int row = e >> 5, kp = e & 31;
                ((u32*)(smc + W2O + row * 144))[kp] =
                    ((const u32*)g_W2f)[(size_t)(h * 128 + row) * 64 + kc * 32 + kp];
            }
            __syncthreads();
#pragma unroll
            for (int ks = 0; ks < 4; ks++) {
                int kk = kc * 4 + ks;
                u32 ah[2][4], al[2][4];
#pragma unroll
                for (int m = 0; m < 2; m++) {
                    ldsm4(ah[m], smb + X1H + arow + (u32)m * 16 * 272 + kk * 32);
                    ldsm4(al[m], smb + X1L + arow + (u32)m * 16 * 272 + kk * 32);
                }
#pragma unroll
                for (int gp = 0; gp < 2; gp++) {
                    u32 bh[2][4];
#pragma unroll
                    for (int gg = 0; gg < 2; gg++)
                        ldsm4(bh[gg], smb + W2O + brow + (u32)(gp * 2 + gg) * 16 * 144 + ks * 32);
#pragma unroll
                    for (int pass = 0; pass < 2; pass++) {
#pragma unroll
                        for (int gg = 0; gg < 2; gg++) {
#pragma unroll
                            for (int t = 0; t < 2; t++) {
                                int n = (gp * 2 + gg) * 2 + t, sb = t * 2;
#pragma unroll
                                for (int m = 0; m < 2; m++) {
                                    const u32* A = (pass == 1) ? al[m] : ah[m];
                                    hmma16(acc[m][n], A, bh[gg][sb], bh[gg][sb + 1]);
                                }
                            }
                        }
                    }
                }
            }
        }

#pragma unroll
        for (int n = 0; n < 8; n++) {
            float v0 = -FLT_BIG, v1 = -FLT_BIG;
            float s0 = 0.f, q0 = 0.f, s1 = 0.f, q1 = 0.f;
#pragma unroll
            for (int m = 0; m < 2; m++) {
                float a0 = acc[m][n][0], a1 = acc[m][n][1], a2 = acc[m][n][2], a3 = acc[m][n][3];
                v0 = fmaxf(v0, fmaxf(a0, a2));
                v1 = fmaxf(v1, fmaxf(a1, a3));
                s0 += a0 + a2; q0 += a0 * a0 + a2 * a2;
                s1 += a1 + a3; q1 += a1 * a1 + a3 * a3;
            }
#pragma unroll
            for (int d = 4; d < 32; d <<= 1) {
                v0 = fmaxf(v0, __shfl_xor_sync(0xffffffffu, v0, d));
                v1 = fmaxf(v1, __shfl_xor_sync(0xffffffffu, v1, d));
                s0 += __shfl_xor_sync(0xffffffffu, s0, d);
                q0 += __shfl_xor_sync(0xffffffffu, q0, d);
                s1 += __shfl_xor_sync(0xffffffffu, s1, d);
                q1 += __shfl_xor_sync(0xffffffffu, q1, d);
            }
            if (lane < 4) {
                int co = h * 128 + cog * 64 + n * 8 + (lane << 1);
                out[OUT_XYZ + ((size_t)b2 * 256 + co) * 1024 + npq] = v0;
                out[OUT_XYZ + ((size_t)b2 * 256 + co + 1) * 1024 + npq] = v1;
                atomicAdd(&g_sum[192 + co], s0);
                atomicAdd(&g_sum[192 + co + 1], s1);
                atomicAdd(&g_sq[192 + co], q0);
                atomicAdd(&g_sq[192 + co + 1], q1);
            }
        }
    }
}

/* inline fold2 + BN2+ReLU in place + xyz gather */
__global__ void k_fx(const float* __restrict__ xyz, const int* __restrict__ smp,
                     const float* __restrict__ gamma, const float* __restrict__ beta,
                     float* __restrict__ out) {
    int i = blockIdx.x * 256 + threadIdx.x;
    const int total = NB * 256 * NPQ;
    if (i < total) {
        int co = (i >> 10) & 255;
        const float inv = 1.0f / (float)PXT;
        float mu = g_sum[192 + co] * inv;
        float var = g_sq[192 + co] * inv - mu * mu;
        float a = gamma[co] * rsqrtf(var + EPSB);
        float c = beta[co] - a * mu;
        float v = out[OUT_XYZ + i];
        out[OUT_XYZ + i] = fmaxf(fmaf(a, v, c), 0.f);
    } else {
        int j = i - total;
        if (j < NB * NPQ) {
            int b = j >> 10;
            const float* s = xyz + (size_t)(b * NPTS + smp[j]) * 3;
            out[j * 3 + 0] = s[0];
            out[j * 3 + 1] = s[1];
            out[j * 3 + 2] = s[2];
        }
    }
}

extern "C" void kernel_launch(void* const* d_in, const int* in_sizes, int n_in,
                              void* d_out, int out_size) {
    const float* xyz = (const float*)d_in[0];
    const float* pts = (const float*)d_in[1];
    const int*   smp = (const int*)d_in[2];
    const int*   nbr = (const int*)d_in[3];
    const float* W0  = (const float*)d_in[4];
    const float* g0  = (const float*)d_in[6];
    const float* be0 = (const float*)d_in[7];
    const float* W1  = (const float*)d_in[8];
    const float* g1  = (const float*)d_in[10];
    const float* be1 = (const float*)d_in[11];
    const float* W2  = (const float*)d_in[12];
    const float* g2  = (const float*)d_in[14];
    const float* be2 = (const float*)d_in[15];
    float* out = (float*)d_out;

    cudaFuncSetAttribute(k_g2f, cudaFuncAttributeMaxDynamicSharedMemorySize, SM2F);

    k_prep<<<128, 256>>>(W1, W2);
    k_pf<<<256, 256>>>(pts, W0);
    k_g0s<<<PXT / 128, 256>>>(xyz, W0, smp, nbr);
    k_m1<<<PXT / 1024, 256>>>(g0, be0, W0, xyz, smp, nbr);
    k_fold1<<<1, 128>>>(W1, g1, be1);
    k_g2f<<<PXT / 128, 256, SM2F>>>(g0, be0, W0, xyz, smp, nbr, out);
    k_fx<<<(NB * 256 * NPQ + NB * NPQ) / 256, 256>>>(xyz, smp, g2, be2, out);
}

// round 16
// speedup vs baseline: 1.1413x; 1.1413x over previous
#include <cuda_runtime.h>
#include <cuda_fp16.h>

#define NPTS  4096
#define NPQ   1024
#define NB    8
#define PXT   262144
#define EPSB  1e-5f
#define OUT_XYZ 24576
#define FLT_BIG 3.4e38f

typedef unsigned int   u32;
typedef unsigned short u16;

/* y1 stored as plain fp16 pairs: [px][64 x u32(co,co+1)]  (64 MB) */
__device__ u32 g_y1p[(size_t)PXT * 64];

/* per-point features pf = W0[:,3:67] @ points : [b*n][64] fp32 (8 MB, L2-resident) */
__device__ float g_pf[(size_t)NB * NPTS * 64];

/* fp16 weight images */
__device__ u16 g_W1f[128 * 64];
__device__ u16 g_W2f[256 * 128];

__device__ float g_sum[448], g_sq[448];

/* ---------- helpers ---------- */
__device__ __forceinline__ u32 pack_f16x2(float lo, float hi) {
    u32 r;
    asm("cvt.rn.f16x2.f32 %0, %1, %2;" : "=r"(r) : "f"(hi), "f"(lo));
    return r;
}
__device__ __forceinline__ void split_pair_f16(float v0, float v1, u32& hp, u32& lp) {
    asm("cvt.rn.f16x2.f32 %0, %1, %2;" : "=r"(hp) : "f"(v1), "f"(v0));
    __half2 h2 = *reinterpret_cast<__half2*>(&hp);
    float d0 = v0 - __half2float(__low2half(h2));
    float d1 = v1 - __half2float(__high2half(h2));
    asm("cvt.rn.f16x2.f32 %0, %1, %2;" : "=r"(lp) : "f"(d1), "f"(d0));
}
__device__ __forceinline__ u32 smem_u32_of(const void* p) {
    u32 a;
    asm("{ .reg .u64 t; cvta.to.shared.u64 t, %1; cvt.u32.u64 %0, t; }" : "=r"(a) : "l"(p));
    return a;
}
__device__ __forceinline__ void ldsm4(u32* r, u32 addr) {
    asm volatile("ldmatrix.sync.aligned.m8n8.x4.shared.b16 {%0,%1,%2,%3}, [%4];"
        : "=r"(r[0]), "=r"(r[1]), "=r"(r[2]), "=r"(r[3]) : "r"(addr));
}
__device__ __forceinline__ void hmma16(float* d, const u32* a, u32 b0, u32 b1) {
    asm volatile("mma.sync.aligned.m16n8k16.row.col.f32.f16.f16.f32 "
        "{%0,%1,%2,%3}, {%4,%5,%6,%7}, {%8,%9}, {%0,%1,%2,%3};"
        : "+f"(d[0]), "+f"(d[1]), "+f"(d[2]), "+f"(d[3])
        : "r"(a[0]), "r"(a[1]), "r"(a[2]), "r"(a[3]), "r"(b0), "r"(b1));
}

extern __shared__ char smc[];

/* ---------- prep ---------- */
__global__ void k_prep(const float* __restrict__ W1, const float* __restrict__ W2) {
    int t0 = blockIdx.x * blockDim.x + threadIdx.x;
    int nth = gridDim.x * blockDim.x;
    for (int t = t0; t < 448; t += nth) { g_sum[t] = 0.f; g_sq[t] = 0.f; }
    for (int e = t0; e < 128 * 64; e += nth) {
        __half h = __float2half_rn(W1[e]);
        g_W1f[e] = *reinterpret_cast<u16*>(&h);
    }
    for (int e = t0; e < 256 * 128; e += nth) {
        __half h = __float2half_rn(W2[e]);
        g_W2f[e] = *reinterpret_cast<u16*>(&h);
    }
}

/* ---------- per-point features ---------- */
__global__ __launch_bounds__(256) void k_pf(const float* __restrict__ pts,
                                            const float* __restrict__ W0) {
    __shared__ float s_f[64][132];
    __shared__ float s_w[64][64];
    int tid = threadIdx.x;
    int b = blockIdx.x >> 5, n0 = (blockIdx.x & 31) * 128;

    for (int e = tid; e < 64 * 32; e += 256) {
        int c = e >> 5, nq = e & 31;
        *(float4*)&s_f[c][nq * 4] =
            *(const float4*)&pts[((size_t)(b * 64 + c)) * NPTS + n0 + nq * 4];
    }
    for (int e = tid; e < 4096; e += 256) {
        int c = e >> 6, co = e & 63;
        s_w[c][co] = W0[co * 67 + 3 + c];
    }
    __syncthreads();

    int coq = tid & 15, nq = tid >> 4;
    float acc[8][4];
#pragma unroll
    for (int i = 0; i < 8; i++)
#pragma unroll
        for (int j = 0; j < 4; j++) acc[i][j] = 0.f;

#pragma unroll 4
    for (int c = 0; c < 64; c++) {
        float4 wv = *(float4*)&s_w[c][coq * 4];
        float fv[8];
        *(float4*)&fv[0] = *(float4*)&s_f[c][nq * 8];
        *(float4*)&fv[4] = *(float4*)&s_f[c][nq * 8 + 4];
        float wj[4] = { wv.x, wv.y, wv.z, wv.w };
#pragma unroll
        for (int i = 0; i < 8; i++)
#pragma unroll
            for (int j = 0; j < 4; j++) acc[i][j] = fmaf(fv[i], wj[j], acc[i][j]);
    }
#pragma unroll
    for (int i = 0; i < 8; i++) {
        int n = n0 + nq * 8 + i;
        *(float4*)&g_pf[((size_t)b * NPTS + n) * 64 + coq * 4] =
            make_float4(acc[i][0], acc[i][1], acc[i][2], acc[i][3]);
    }
}

/* ========= layer 0 stats ONLY ========= */
__global__ __launch_bounds__(256) void k_g0s(
    const float* __restrict__ xyz, const float* __restrict__ W0,
    const int* __restrict__ smp, const int* __restrict__ nbr)
{
    __shared__ float s_R[3][64];
    __shared__ float s_sum[64], s_sq[64];
    int tid = threadIdx.x;
    int px0 = blockIdx.x * 128, b = px0 >> 15;

    if (tid < 192) {
        int k = tid >> 6, co = tid & 63;
        s_R[k][co] = W0[co * 67 + k];
    }
    if (tid < 64) { s_sum[tid] = 0.f; s_sq[tid] = 0.f; }
    __syncthreads();

    int co = tid & 63, pxq = tid >> 6;
    float rk0 = s_R[0][co], rk1 = s_R[1][co], rk2 = s_R[2][co];

    int si = smp[(px0 >> 5) + pxq];
    const float* xc = xyz + (size_t)(b * NPTS + si) * 3;
    float c0 = xc[0], c1 = xc[1], c2 = xc[2];

    float ssum = 0.f, ssq = 0.f;
#pragma unroll 4
    for (int i = 0; i < 32; i++) {
        int pxg = px0 + pxq * 32 + i;
        int ni = nbr[pxg];
        const float* xn = xyz + (size_t)(b * NPTS + ni) * 3;
        float r0 = xn[0] - c0, r1 = xn[1] - c1, r2 = xn[2] - c2;
        float pf = g_pf[((size_t)b * NPTS + ni) * 64 + co];
        float y = fmaf(rk0, r0, fmaf(rk1, r1, fmaf(rk2, r2, pf)));
        ssum += y; ssq += y * y;
    }
    atomicAdd(&s_sum[co], ssum);
    atomicAdd(&s_sq[co], ssq);
    __syncthreads();
    if (tid < 64) {
        atomicAdd(&g_sum[tid], s_sum[tid]);
        atomicAdd(&g_sq[tid], s_sq[tid]);
    }
}

/* ========== layer 1: recompute-y0 staging (fp16 split), fp16 W, 2-pass,
   GEMM(px128 x co128 x k64) + stats1; y1 stored plain fp16 ========== */
__global__ __launch_bounds__(256, 3) void k_g1(
    const float* __restrict__ gamma, const float* __restrict__ beta,
    const float* __restrict__ W0, const float* __restrict__ xyz,
    const int* __restrict__ smp, const int* __restrict__ nbr)
{
    const int XHo = 0, XLo = 18432, WHo = 36864;
    u16* WH = (u16*)(smc + WHo);
    float4* s_cf = (float4*)(smc + 55296);
    float*  s_cc = (float*)(smc + 55296 + 1024);

    int tid = threadIdx.x, wid = tid >> 5, lane = tid & 31;
    int px0 = blockIdx.x * 128, b = px0 >> 15;

    if (tid < 64) {
        const float inv = 1.0f / (float)PXT;
        float mu = g_sum[tid] * inv;
        float var = g_sq[tid] * inv - mu * mu;
        float a = gamma[tid] * rsqrtf(var + EPSB);
        float4 cf;
        cf.x = a;
        cf.y = a * W0[tid * 67 + 0];
        cf.z = a * W0[tid * 67 + 1];
        cf.w = a * W0[tid * 67 + 2];
        s_cf[tid] = cf;
        s_cc[tid] = beta[tid] - a * mu;
    }
    for (int e = tid; e < 4096; e += 256) {
        int row = e >> 5, kp = e & 31;
        ((u32*)(WH + row * 72))[kp] = ((const u32*)g_W1f)[row * 32 + kp];
    }
    __syncthreads();
    {
        int r = tid >> 1, half = tid & 1;
        int px = px0 + r;
        int ni = nbr[px];
        int si = smp[px >> 5];
        const float* xn = xyz + (size_t)(b * NPTS + ni) * 3;
        const float* xc = xyz + (size_t)(b * NPTS + si) * 3;
        float r0 = xn[0] - xc[0], r1 = xn[1] - xc[1], r2 = xn[2] - xc[2];
        const float4* pf4 = (const float4*)&g_pf[((size_t)b * NPTS + ni) * 64 + half * 32];
        u32* xh = (u32*)(smc + XHo + r * 144 + half * 64);
        u32* xl = (u32*)(smc + XLo + r * 144 + half * 64);
#pragma unroll
        for (int j = 0; j < 8; j++) {
            float4 p = pf4[j];
            int k = half * 32 + j * 4;
            float4 c0 = s_cf[k], c1 = s_cf[k + 1], c2 = s_cf[k + 2], c3 = s_cf[k + 3];
            float v0 = fmaxf(fmaf(c0.x, p.x, fmaf(c0.y, r0, fmaf(c0.z, r1, fmaf(c0.w, r2, s_cc[k])))), 0.f);
            float v1 = fmaxf(fmaf(c1.x, p.y, fmaf(c1.y, r0, fmaf(c1.z, r1, fmaf(c1.w, r2, s_cc[k + 1])))), 0.f);
            float v2 = fmaxf(fmaf(c2.x, p.z, fmaf(c2.y, r0, fmaf(c2.z, r1, fmaf(c2.w, r2, s_cc[k + 2])))), 0.f);
            float v3 = fmaxf(fmaf(c3.x, p.w, fmaf(c3.y, r0, fmaf(c3.z, r1, fmaf(c3.w, r2, s_cc[k + 3])))), 0.f);
            split_pair_f16(v0, v1, xh[j * 2], xl[j * 2]);
            split_pair_f16(v2, v3, xh[j * 2 + 1], xl[j * 2 + 1]);
        }
    }
    __syncthreads();

    int pxg = wid >> 1, cog = wid & 1;
    u32 smb = smem_u32_of(smc);
    u32 arow = (u32)(pxg * 32 + (lane & 15)) * 144 + ((lane >> 4) << 4);

    for (int ch = 0; ch < 2; ch++) {
        u32 brow = (u32)(cog * 64 + ch * 32 + ((lane >> 4) << 3) + (lane & 7)) * 144
                 + (((lane >> 3) & 1) << 4);

        float acc[2][4][4];
#pragma unroll
        for (int m = 0; m < 2; m++)
#pragma unroll
            for (int n = 0; n < 4; n++)
#pragma unroll
                for (int i = 0; i < 4; i++) acc[m][n][i] = 0.f;

#pragma unroll
        for (int ks = 0; ks < 4; ks++) {
            u32 ah[2][4], al[2][4], bh[2][4];
#pragma unroll
            for (int m = 0; m < 2; m++) {
                ldsm4(ah[m], smb + XHo + arow + (u32)m * 16 * 144 + ks * 32);
                ldsm4(al[m], smb + XLo + arow + (u32)m * 16 * 144 + ks * 32);
            }
#pragma unroll
            for (int gg = 0; gg < 2; gg++)
                ldsm4(bh[gg], smb + WHo + brow + (u32)gg * 16 * 144 + ks * 32);
#pragma unroll
            for (int pass = 0; pass < 2; pass++) {
#pragma unroll
                for (int gg = 0; gg < 2; gg++) {
#pragma unroll
                    for (int t = 0; t < 2; t++) {
                        int n = gg * 2 + t, sb = t * 2;
#pragma unroll
                        for (int m = 0; m < 2; m++) {
                            const u32* A = (pass == 1) ? al[m] : ah[m];
                            hmma16(acc[m][n], A, bh[gg][sb], bh[gg][sb + 1]);
                        }
                    }
                }
            }
        }

#pragma unroll
        for (int n = 0; n < 4; n++) {
            float s0 = 0.f, q0 = 0.f, s1 = 0.f, q1 = 0.f;
#pragma unroll
            for (int m = 0; m < 2; m++) {
                int px = px0 + pxg * 32 + m * 16 + (lane >> 2);
                int co = cog * 64 + ch * 32 + n * 8 + ((lane & 3) << 1);
                g_y1p[(size_t)px * 64 + (co >> 1)] = pack_f16x2(acc[m][n][0], acc[m][n][1]);
                g_y1p[(size_t)(px + 8) * 64 + (co >> 1)] = pack_f16x2(acc[m][n][2], acc[m][n][3]);
                float a0 = acc[m][n][0], a1 = acc[m][n][1], a2 = acc[m][n][2], a3 = acc[m][n][3];
                s0 += a0 + a2; q0 += a0 * a0 + a2 * a2;
                s1 += a1 + a3; q1 += a1 * a1 + a3 * a3;
            }
#pragma unroll
            for (int d = 4; d < 32; d <<= 1) {
                s0 += __shfl_xor_sync(0xffffffffu, s0, d);
                q0 += __shfl_xor_sync(0xffffffffu, q0, d);
                s1 += __shfl_xor_sync(0xffffffffu, s1, d);
                q1 += __shfl_xor_sync(0xffffffffu, q1, d);
            }
            if (lane < 4) {
                int co = cog * 64 + ch * 32 + n * 8 + (lane << 1);
                atomicAdd(&g_sum[64 + co], s0);
                atomicAdd(&g_sum[64 + co + 1], s1);
                atomicAdd(&g_sq[64 + co], q0);
                atomicAdd(&g_sq[64 + co + 1], q1);
            }
        }
    }
}

/* == layer 2: fp16 2-pass, X staged once from fp16 y1, W2 single-staged per half,
   GEMM(px128 x co256 x k128) + stats2 + NS-max == */
#define X1H 0
#define X1L 34816
#define W2O 69632
#define SA2 104448
#define SC2 104960
#define SM2 105472

__global__ __launch_bounds__(256, 2) void k_g2(const float* __restrict__ gamma,
                                               const float* __restrict__ beta,
                                               float* __restrict__ out)
{
    float* s_a = (float*)(smc + SA2);
    float* s_c = (float*)(smc + SC2);

    int tid = threadIdx.x, wid = tid >> 5, lane = tid & 31;
    int px0 = blockIdx.x * 128;

    if (tid < 128) {
        const float inv = 1.0f / (float)PXT;
        float mu = g_sum[64 + tid] * inv;
        float var = g_sq[64 + tid] * inv - mu * mu;
        float a = gamma[tid] * rsqrtf(var + EPSB);
        s_a[tid] = a;
        s_c[tid] = beta[tid] - a * mu;
    }
    __syncthreads();
    {
        int r = tid >> 1, half = tid & 1;
        int px = px0 + r;
        const uint4* src = (const uint4*)&g_y1p[(size_t)px * 64 + half * 32];
        u32* xh = (u32*)(smc + X1H + r * 272 + half * 128);
        u32* xl = (u32*)(smc + X1L + r * 272 + half * 128);
#pragma unroll
        for (int j = 0; j < 8; j++) {
            uint4 w = src[j];
            u32 ww[4] = { w.x, w.y, w.z, w.w };
            int kb = half * 64 + j * 8;
#pragma unroll
            for (int q = 0; q < 4; q++) {
                __half2 h2 = *reinterpret_cast<__half2*>(&ww[q]);
                int k = kb + q * 2;
                float v0 = fmaxf(fmaf(s_a[k],     __half2float(__low2half(h2)),  s_c[k]),     0.f);
                float v1 = fmaxf(fmaf(s_a[k + 1], __half2float(__high2half(h2)), s_c[k + 1]), 0.f);
                split_pair_f16(v0, v1, xh[j * 4 + q], xl[j * 4 + q]);
            }
        }
    }

    int pxg = wid >> 1, cog = wid & 1;
    u32 smb = smem_u32_of(smc);
    u32 arow = (u32)(pxg * 32 + (lane & 15)) * 272 + ((lane >> 4) << 4);
    u32 brow = (u32)(cog * 64 + ((lane >> 4) << 3) + (lane & 7)) * 272 + (((lane >> 3) & 1) << 4);

    int np = blockIdx.x * 4 + pxg;
    int b = np >> 10, npq = np & 1023;

    for (int h = 0; h < 2; h++) {
        float acc[2][8][4];
#pragma unroll
        for (int m = 0; m < 2; m++)
#pragma unroll
            for (int n = 0; n < 8; n++)
#pragma unroll
                for (int i = 0; i < 4; i++) acc[m][n][i] = 0.f;

        __syncthreads();   /* X1 staged (h=0) / prior W reads done (h=1) */
        for (int e = tid; e < 8192; e += 256) {
            int row = e >> 6, kp = e & 63;
            ((u32*)(smc + W2O + row * 272))[kp] =
                ((const u32*)g_W2f)[(size_t)(h * 128 + row) * 64 + kp];
        }
        __syncthreads();

#pragma unroll
        for (int ks = 0; ks < 8; ks++) {
            u32 ah[2][4], al[2][4];
#pragma unroll
            for (int m = 0; m < 2; m++) {
                ldsm4(ah[m], smb + X1H + arow + (u32)m * 16 * 272 + ks * 32);
                ldsm4(al[m], smb + X1L + arow + (u32)m * 16 * 272 + ks * 32);
            }
#pragma unroll
            for (int gp = 0; gp < 2; gp++) {
                u32 bh[2][4];
#pragma unroll
                for (int gg = 0; gg < 2; gg++)
                    ldsm4(bh[gg], smb + W2O + brow + (u32)(gp * 2 + gg) * 16 * 272 + ks * 32);
#pragma unroll
                for (int pass = 0; pass < 2; pass++) {
#pragma unroll
                    for (int gg = 0; gg < 2; gg++) {
#pragma unroll
                        for (int t = 0; t < 2; t++) {
                            int n = (gp * 2 + gg) * 2 + t, sb = t * 2;
#pragma unroll
                            for (int m = 0; m < 2; m++) {
                                const u32* A = (pass == 1) ? al[m] : ah[m];
                                hmma16(acc[m][n], A, bh[gg][sb], bh[gg][sb + 1]);
                            }
                        }
                    }
                }
            }
        }

#pragma unroll
        for (int n = 0; n < 8; n++) {
            float v0 = -FLT_BIG, v1 = -FLT_BIG;
            float s0 = 0.f, q0 = 0.f, s1 = 0.f, q1 = 0.f;
#pragma unroll
            for (int m = 0; m < 2; m++) {
                float a0 = acc[m][n][0], a1 = acc[m][n][1], a2 = acc[m][n][2], a3 = acc[m][n][3];
                v0 = fmaxf(v0, fmaxf(a0, a2));
                v1 = fmaxf(v1, fmaxf(a1, a3));
                s0 += a0 + a2; q0 += a0 * a0 + a2 * a2;
                s1 += a1 + a3; q1 += a1 * a1 + a3 * a3;
            }
#pragma unroll
            for (int d = 4; d < 32; d <<= 1) {
                v0 = fmaxf(v0, __shfl_xor_sync(0xffffffffu, v0, d));
                v1 = fmaxf(v1, __shfl_xor_sync(0xffffffffu, v1, d));
                s0 += __shfl_xor_sync(0xffffffffu, s0, d);
                q0 += __shfl_xor_sync(0xffffffffu, q0, d);
                s1 += __shfl_xor_sync(0xffffffffu, s1, d);
                q1 += __shfl_xor_sync(0xffffffffu, q1, d);
            }
            if (lane < 4) {
                int co = h * 128 + cog * 64 + n * 8 + (lane << 1);
                out[OUT_XYZ + ((size_t)b * 256 + co) * 1024 + npq] = v0;
                out[OUT_XYZ + ((size_t)b * 256 + co + 1) * 1024 + npq] = v1;
                atomicAdd(&g_sum[192 + co], s0);
                atomicAdd(&g_sum[192 + co + 1], s1);
                atomicAdd(&g_sq[192 + co], q0);
                atomicAdd(&g_sq[192 + co + 1], q1);
            }
        }
    }
}

/* inline fold2 + BN2+ReLU in place + xyz gather */
__global__ void k_fx(const float* __restrict__ xyz, const int* __restrict__ smp,
                     const float* __restrict__ gamma, const float* __restrict__ beta,
                     float* __restrict__ out) {
    int i = blockIdx.x * 256 + threadIdx.x;
    const int total = NB * 256 * NPQ;
    if (i < total) {
        int co = (i >> 10) & 255;
        const float inv = 1.0f / (float)PXT;
        float mu = g_sum[192 + co] * inv;
        float var = g_sq[192 + co] * inv - mu * mu;
        float a = gamma[co] * rsqrtf(var + EPSB);
        float c = beta[co] - a * mu;
        float v = out[OUT_XYZ + i];
        out[OUT_XYZ + i] = fmaxf(fmaf(a, v, c), 0.f);
    } else {
        int j = i - total;
        if (j < NB * NPQ) {
            int b = j >> 10;
            const float* s = xyz + (size_t)(b * NPTS + smp[j]) * 3;
            out[j * 3 + 0] = s[0];
            out[j * 3 + 1] = s[1];
            out[j * 3 + 2] = s[2];
        }
    }
}

extern "C" void kernel_launch(void* const* d_in, const int* in_sizes, int n_in,
                              void* d_out, int out_size) {
    const float* xyz = (const float*)d_in[0];
    const float* pts = (const float*)d_in[1];
    const int*   smp = (const int*)d_in[2];
    const int*   nbr = (const int*)d_in[3];
    const float* W0  = (const float*)d_in[4];
    const float* g0  = (const float*)d_in[6];
    const float* be0 = (const float*)d_in[7];
    const float* W1  = (const float*)d_in[8];
    const float* g1  = (const float*)d_in[10];
    const float* be1 = (const float*)d_in[11];
    const float* W2  = (const float*)d_in[12];
    const float* g2  = (const float*)d_in[14];
    const float* be2 = (const float*)d_in[15];
    float* out = (float*)d_out;

    const int SM1 = 56576;
    cudaFuncSetAttribute(k_g1, cudaFuncAttributeMaxDynamicSharedMemorySize, SM1);
    cudaFuncSetAttribute(k_g2, cudaFuncAttributeMaxDynamicSharedMemorySize, SM2);

    k_prep<<<128, 256>>>(W1, W2);
    k_pf<<<256, 256>>>(pts, W0);
    k_g0s<<<PXT / 128, 256>>>(xyz, W0, smp, nbr);
    k_g1<<<PXT / 128, 256, SM1>>>(g0, be0, W0, xyz, smp, nbr);
    k_g2<<<PXT / 128, 256, SM2>>>(g1, be1, out);
    k_fx<<<(NB * 256 * NPQ + NB * NPQ) / 256, 256>>>(xyz, smp, g2, be2, out);
}

// round 17
// speedup vs baseline: 1.1541x; 1.0112x over previous
#include <cuda_runtime.h>
#include <cuda_fp16.h>

#define NPTS  4096
#define NPQ   1024
#define NB    8
#define PXT   262144
#define EPSB  1e-5f
#define OUT_XYZ 24576
#define FLT_BIG 3.4e38f

typedef unsigned int   u32;
typedef unsigned short u16;

/* y1 stored as plain fp16 pairs: [px][64 x u32(co,co+1)]  (64 MB) */
__device__ u32 g_y1p[(size_t)PXT * 64];

/* per-point features pf = W0[:,3:67] @ points : [b*n][64] fp32 (8 MB, L2-resident) */
__device__ float g_pf[(size_t)NB * NPTS * 64];

/* fp16 weight images */
__device__ u16 g_W1f[128 * 64];
__device__ u16 g_W2f[256 * 128];

__device__ float g_sum[448], g_sq[448];

/* ---------- helpers ---------- */
__device__ __forceinline__ u32 pack_f16x2(float lo, float hi) {
    u32 r;
    asm("cvt.rn.f16x2.f32 %0, %1, %2;" : "=r"(r) : "f"(hi), "f"(lo));
    return r;
}
__device__ __forceinline__ void split_pair_f16(float v0, float v1, u32& hp, u32& lp) {
    asm("cvt.rn.f16x2.f32 %0, %1, %2;" : "=r"(hp) : "f"(v1), "f"(v0));
    __half2 h2 = *reinterpret_cast<__half2*>(&hp);
    float d0 = v0 - __half2float(__low2half(h2));
    float d1 = v1 - __half2float(__high2half(h2));
    asm("cvt.rn.f16x2.f32 %0, %1, %2;" : "=r"(lp) : "f"(d1), "f"(d0));
}
__device__ __forceinline__ u32 smem_u32_of(const void* p) {
    u32 a;
    asm("{ .reg .u64 t; cvta.to.shared.u64 t, %1; cvt.u32.u64 %0, t; }" : "=r"(a) : "l"(p));
    return a;
}
__device__ __forceinline__ void ldsm4(u32* r, u32 addr) {
    asm volatile("ldmatrix.sync.aligned.m8n8.x4.shared.b16 {%0,%1,%2,%3}, [%4];"
        : "=r"(r[0]), "=r"(r[1]), "=r"(r[2]), "=r"(r[3]) : "r"(addr));
}
__device__ __forceinline__ void hmma16(float* d, const u32* a, u32 b0, u32 b1) {
    asm volatile("mma.sync.aligned.m16n8k16.row.col.f32.f16.f16.f32 "
        "{%0,%1,%2,%3}, {%4,%5,%6,%7}, {%8,%9}, {%0,%1,%2,%3};"
        : "+f"(d[0]), "+f"(d[1]), "+f"(d[2]), "+f"(d[3])
        : "r"(a[0]), "r"(a[1]), "r"(a[2]), "r"(a[3]), "r"(b0), "r"(b1));
}

extern __shared__ char smc[];

/* ---------- prep ---------- */
__global__ void k_prep(const float* __restrict__ W1, const float* __restrict__ W2) {
    int t0 = blockIdx.x * blockDim.x + threadIdx.x;
    int nth = gridDim.x * blockDim.x;
    for (int t = t0; t < 448; t += nth) { g_sum[t] = 0.f; g_sq[t] = 0.f; }
    for (int e = t0; e < 128 * 64; e += nth) {
        __half h = __float2half_rn(W1[e]);
        g_W1f[e] = *reinterpret_cast<u16*>(&h);
    }
    for (int e = t0; e < 256 * 128; e += nth) {
        __half h = __float2half_rn(W2[e]);
        g_W2f[e] = *reinterpret_cast<u16*>(&h);
    }
}

/* ---------- per-point features ---------- */
__global__ __launch_bounds__(256) void k_pf(const float* __restrict__ pts,
                                            const float* __restrict__ W0) {
    __shared__ float s_f[64][132];
    __shared__ float s_w[64][64];
    int tid = threadIdx.x;
    int b = blockIdx.x >> 5, n0 = (blockIdx.x & 31) * 128;

    for (int e = tid; e < 64 * 32; e += 256) {
        int c = e >> 5, nq = e & 31;
        *(float4*)&s_f[c][nq * 4] =
            *(const float4*)&pts[((size_t)(b * 64 + c)) * NPTS + n0 + nq * 4];
    }
    for (int e = tid; e < 4096; e += 256) {
        int c = e >> 6, co = e & 63;
        s_w[c][co] = W0[co * 67 + 3 + c];
    }
    __syncthreads();

    int coq = tid & 15, nq = tid >> 4;
    float acc[8][4];
#pragma unroll
    for (int i = 0; i < 8; i++)
#pragma unroll
        for (int j = 0; j < 4; j++) acc[i][j] = 0.f;

#pragma unroll 4
    for (int c = 0; c < 64; c++) {
        float4 wv = *(float4*)&s_w[c][coq * 4];
        float fv[8];
        *(float4*)&fv[0] = *(float4*)&s_f[c][nq * 8];
        *(float4*)&fv[4] = *(float4*)&s_f[c][nq * 8 + 4];
        float wj[4] = { wv.x, wv.y, wv.z, wv.w };
#pragma unroll
        for (int i = 0; i < 8; i++)
#pragma unroll
            for (int j = 0; j < 4; j++) acc[i][j] = fmaf(fv[i], wj[j], acc[i][j]);
    }
#pragma unroll
    for (int i = 0; i < 8; i++) {
        int n = n0 + nq * 8 + i;
        *(float4*)&g_pf[((size_t)b * NPTS + n) * 64 + coq * 4] =
            make_float4(acc[i][0], acc[i][1], acc[i][2], acc[i][3]);
    }
}

/* ========= layer 0 stats ONLY ========= */
__global__ __launch_bounds__(256) void k_g0s(
    const float* __restrict__ xyz, const float* __restrict__ W0,
    const int* __restrict__ smp, const int* __restrict__ nbr)
{
    __shared__ float s_R[3][64];
    __shared__ float s_sum[64], s_sq[64];
    int tid = threadIdx.x;
    int px0 = blockIdx.x * 128, b = px0 >> 15;

    if (tid < 192) {
        int k = tid >> 6, co = tid & 63;
        s_R[k][co] = W0[co * 67 + k];
    }
    if (tid < 64) { s_sum[tid] = 0.f; s_sq[tid] = 0.f; }
    __syncthreads();

    int co = tid & 63, pxq = tid >> 6;
    float rk0 = s_R[0][co], rk1 = s_R[1][co], rk2 = s_R[2][co];

    int si = smp[(px0 >> 5) + pxq];
    const float* xc = xyz + (size_t)(b * NPTS + si) * 3;
    float c0 = xc[0], c1 = xc[1], c2 = xc[2];

    float ssum = 0.f, ssq = 0.f;
#pragma unroll 4
    for (int i = 0; i < 32; i++) {
        int pxg = px0 + pxq * 32 + i;
        int ni = nbr[pxg];
        const float* xn = xyz + (size_t)(b * NPTS + ni) * 3;
        float r0 = xn[0] - c0, r1 = xn[1] - c1, r2 = xn[2] - c2;
        float pf = g_pf[((size_t)b * NPTS + ni) * 64 + co];
        float y = fmaf(rk0, r0, fmaf(rk1, r1, fmaf(rk2, r2, pf)));
        ssum += y; ssq += y * y;
    }
    atomicAdd(&s_sum[co], ssum);
    atomicAdd(&s_sq[co], ssq);
    __syncthreads();
    if (tid < 64) {
        atomicAdd(&g_sum[tid], s_sum[tid]);
        atomicAdd(&g_sq[tid], s_sq[tid]);
    }
}

/* ========== layer 1: recompute-y0 staging (fp16 split), fp16 W, 2-pass,
   GEMM(px128 x co128 x k64) + stats1; y1 stored plain fp16 ========== */
__global__ __launch_bounds__(256, 3) void k_g1(
    const float* __restrict__ gamma, const float* __restrict__ beta,
    const float* __restrict__ W0, const float* __restrict__ xyz,
    const int* __restrict__ smp, const int* __restrict__ nbr)
{
    const int XHo = 0, XLo = 18432, WHo = 36864;
    u16* WH = (u16*)(smc + WHo);
    float4* s_cf = (float4*)(smc + 55296);
    float*  s_cc = (float*)(smc + 55296 + 1024);

    int tid = threadIdx.x, wid = tid >> 5, lane = tid & 31;
    int px0 = blockIdx.x * 128, b = px0 >> 15;

    if (tid < 64) {
        const float inv = 1.0f / (float)PXT;
        float mu = g_sum[tid] * inv;
        float var = g_sq[tid] * inv - mu * mu;
        float a = gamma[tid] * rsqrtf(var + EPSB);
        float4 cf;
        cf.x = a;
        cf.y = a * W0[tid * 67 + 0];
        cf.z = a * W0[tid * 67 + 1];
        cf.w = a * W0[tid * 67 + 2];
        s_cf[tid] = cf;
        s_cc[tid] = beta[tid] - a * mu;
    }
    for (int e = tid; e < 4096; e += 256) {
        int row = e >> 5, kp = e & 31;
        ((u32*)(WH + row * 72))[kp] = ((const u32*)g_W1f)[row * 32 + kp];
    }
    __syncthreads();
    {
        int r = tid >> 1, half = tid & 1;
        int px = px0 + r;
        int ni = nbr[px];
        int si = smp[px >> 5];
        const float* xn = xyz + (size_t)(b * NPTS + ni) * 3;
        const float* xc = xyz + (size_t)(b * NPTS + si) * 3;
        float r0 = xn[0] - xc[0], r1 = xn[1] - xc[1], r2 = xn[2] - xc[2];
        const float4* pf4 = (const float4*)&g_pf[((size_t)b * NPTS + ni) * 64 + half * 32];
        u32* xh = (u32*)(smc + XHo + r * 144 + half * 64);
        u32* xl = (u32*)(smc + XLo + r * 144 + half * 64);
#pragma unroll
        for (int j = 0; j < 8; j++) {
            float4 p = pf4[j];
            int k = half * 32 + j * 4;
            float4 c0 = s_cf[k], c1 = s_cf[k + 1], c2 = s_cf[k + 2], c3 = s_cf[k + 3];
            float v0 = fmaxf(fmaf(c0.x, p.x, fmaf(c0.y, r0, fmaf(c0.z, r1, fmaf(c0.w, r2, s_cc[k])))), 0.f);
            float v1 = fmaxf(fmaf(c1.x, p.y, fmaf(c1.y, r0, fmaf(c1.z, r1, fmaf(c1.w, r2, s_cc[k + 1])))), 0.f);
            float v2 = fmaxf(fmaf(c2.x, p.z, fmaf(c2.y, r0, fmaf(c2.z, r1, fmaf(c2.w, r2, s_cc[k + 2])))), 0.f);
            float v3 = fmaxf(fmaf(c3.x, p.w, fmaf(c3.y, r0, fmaf(c3.z, r1, fmaf(c3.w, r2, s_cc[k + 3])))), 0.f);
            split_pair_f16(v0, v1, xh[j * 2], xl[j * 2]);
            split_pair_f16(v2, v3, xh[j * 2 + 1], xl[j * 2 + 1]);
        }
    }
    __syncthreads();

    int pxg = wid >> 1, cog = wid & 1;
    u32 smb = smem_u32_of(smc);
    u32 arow = (u32)(pxg * 32 + (lane & 15)) * 144 + ((lane >> 4) << 4);

    for (int ch = 0; ch < 2; ch++) {
        u32 brow = (u32)(cog * 64 + ch * 32 + ((lane >> 4) << 3) + (lane & 7)) * 144
                 + (((lane >> 3) & 1) << 4);

        float acc[2][4][4];
#pragma unroll
        for (int m = 0; m < 2; m++)
#pragma unroll
            for (int n = 0; n < 4; n++)
#pragma unroll
                for (int i = 0; i < 4; i++) acc[m][n][i] = 0.f;

#pragma unroll
        for (int ks = 0; ks < 4; ks++) {
            u32 ah[2][4], al[2][4], bh[2][4];
#pragma unroll
            for (int m = 0; m < 2; m++) {
                ldsm4(ah[m], smb + XHo + arow + (u32)m * 16 * 144 + ks * 32);
                ldsm4(al[m], smb + XLo + arow + (u32)m * 16 * 144 + ks * 32);
            }
#pragma unroll
            for (int gg = 0; gg < 2; gg++)
                ldsm4(bh[gg], smb + WHo + brow + (u32)gg * 16 * 144 + ks * 32);
#pragma unroll
            for (int pass = 0; pass < 2; pass++) {
#pragma unroll
                for (int gg = 0; gg < 2; gg++) {
#pragma unroll
                    for (int t = 0; t < 2; t++) {
                        int n = gg * 2 + t, sb = t * 2;
#pragma unroll
                        for (int m = 0; m < 2; m++) {
                            const u32* A = (pass == 1) ? al[m] : ah[m];
                            hmma16(acc[m][n], A, bh[gg][sb], bh[gg][sb + 1]);
                        }
                    }
                }
            }
        }

#pragma unroll
        for (int n = 0; n < 4; n++) {
            float s0 = 0.f, q0 = 0.f, s1 = 0.f, q1 = 0.f;
#pragma unroll
            for (int m = 0; m < 2; m++) {
                int px = px0 + pxg * 32 + m * 16 + (lane >> 2);
                int co = cog * 64 + ch * 32 + n * 8 + ((lane & 3) << 1);
                g_y1p[(size_t)px * 64 + (co >> 1)] = pack_f16x2(acc[m][n][0], acc[m][n][1]);
                g_y1p[(size_t)(px + 8) * 64 + (co >> 1)] = pack_f16x2(acc[m][n][2], acc[m][n][3]);
                float a0 = acc[m][n][0], a1 = acc[m][n][1], a2 = acc[m][n][2], a3 = acc[m][n][3];
                s0 += a0 + a2; q0 += a0 * a0 + a2 * a2;
                s1 += a1 + a3; q1 += a1 * a1 + a3 * a3;
            }
#pragma unroll
            for (int d = 4; d < 32; d <<= 1) {
                s0 += __shfl_xor_sync(0xffffffffu, s0, d);
                q0 += __shfl_xor_sync(0xffffffffu, q0, d);
                s1 += __shfl_xor_sync(0xffffffffu, s1, d);
                q1 += __shfl_xor_sync(0xffffffffu, q1, d);
            }
            if (lane < 4) {
                int co = cog * 64 + ch * 32 + n * 8 + (lane << 1);
                atomicAdd(&g_sum[64 + co], s0);
                atomicAdd(&g_sum[64 + co + 1], s1);
                atomicAdd(&g_sq[64 + co], q0);
                atomicAdd(&g_sq[64 + co + 1], q1);
            }
        }
    }
}

/* == layer 2: X1 single fp16 (1-pass), W2 fp16, GEMM(px128 x co256 x k128)
   + stats2 + NS-max == */
#define X1H 0
#define W2O 34816
#define SA2 69632
#define SC2 70144
#define SM2 70656

__global__ __launch_bounds__(256, 2) void k_g2(const float* __restrict__ gamma,
                                               const float* __restrict__ beta,
                                               float* __restrict__ out)
{
    float* s_a = (float*)(smc + SA2);
    float* s_c = (float*)(smc + SC2);

    int tid = threadIdx.x, wid = tid >> 5, lane = tid & 31;
    int px0 = blockIdx.x * 128;

    if (tid < 128) {
        const float inv = 1.0f / (float)PXT;
        float mu = g_sum[64 + tid] * inv;
        float var = g_sq[64 + tid] * inv - mu * mu;
        float a = gamma[tid] * rsqrtf(var + EPSB);
        s_a[tid] = a;
        s_c[tid] = beta[tid] - a * mu;
    }
    __syncthreads();
    {
        int r = tid >> 1, half = tid & 1;
        int px = px0 + r;
        const uint4* src = (const uint4*)&g_y1p[(size_t)px * 64 + half * 32];
        u32* xh = (u32*)(smc + X1H + r * 272 + half * 128);
#pragma unroll
        for (int j = 0; j < 8; j++) {
            uint4 w = src[j];
            u32 ww[4] = { w.x, w.y, w.z, w.w };
            int kb = half * 64 + j * 8;
#pragma unroll
            for (int q = 0; q < 4; q++) {
                __half2 h2 = *reinterpret_cast<__half2*>(&ww[q]);
                int k = kb + q * 2;
                float v0 = fmaxf(fmaf(s_a[k],     __half2float(__low2half(h2)),  s_c[k]),     0.f);
                float v1 = fmaxf(fmaf(s_a[k + 1], __half2float(__high2half(h2)), s_c[k + 1]), 0.f);
                xh[j * 4 + q] = pack_f16x2(v0, v1);
            }
        }
    }

    int pxg = wid >> 1, cog = wid & 1;
    u32 smb = smem_u32_of(smc);
    u32 arow = (u32)(pxg * 32 + (lane & 15)) * 272 + ((lane >> 4) << 4);
    u32 brow = (u32)(cog * 64 + ((lane >> 4) << 3) + (lane & 7)) * 272 + (((lane >> 3) & 1) << 4);

    int np = blockIdx.x * 4 + pxg;
    int b = np >> 10, npq = np & 1023;

    for (int h = 0; h < 2; h++) {
        float acc[2][8][4];
#pragma unroll
        for (int m = 0; m < 2; m++)
#pragma unroll
            for (int n = 0; n < 8; n++)
#pragma unroll
                for (int i = 0; i < 4; i++) acc[m][n][i] = 0.f;

        __syncthreads();   /* X1 staged (h=0) / prior W reads done (h=1) */
        for (int e = tid; e < 8192; e += 256) {
            int row = e >> 6, kp = e & 63;
            ((u32*)(smc + W2O + row * 272))[kp] =
                ((const u32*)g_W2f)[(size_t)(h * 128 + row) * 64 + kp];
        }
        __syncthreads();

#pragma unroll
        for (int ks = 0; ks < 8; ks++) {
            u32 ah[2][4];
#pragma unroll
            for (int m = 0; m < 2; m++)
                ldsm4(ah[m], smb + X1H + arow + (u32)m * 16 * 272 + ks * 32);
#pragma unroll
            for (int gp = 0; gp < 2; gp++) {
                u32 bh[2][4];
#pragma unroll
                for (int gg = 0; gg < 2; gg++)
                    ldsm4(bh[gg], smb + W2O + brow + (u32)(gp * 2 + gg) * 16 * 272 + ks * 32);
#pragma unroll
                for (int gg = 0; gg < 2; gg++) {
#pragma unroll
                    for (int t = 0; t < 2; t++) {
                        int n = (gp * 2 + gg) * 2 + t, sb = t * 2;
#pragma unroll
                        for (int m = 0; m < 2; m++)
                            hmma16(acc[m][n], ah[m], bh[gg][sb], bh[gg][sb + 1]);
                    }
                }
            }
        }

#pragma unroll
        for (int n = 0; n < 8; n++) {
            float v0 = -FLT_BIG, v1 = -FLT_BIG;
            float s0 = 0.f, q0 = 0.f, s1 = 0.f, q1 = 0.f;
#pragma unroll
            for (int m = 0; m < 2; m++) {
                float a0 = acc[m][n][0], a1 = acc[m][n][1], a2 = acc[m][n][2], a3 = acc[m][n][3];
                v0 = fmaxf(v0, fmaxf(a0, a2));
                v1 = fmaxf(v1, fmaxf(a1, a3));
                s0 += a0 + a2; q0 += a0 * a0 + a2 * a2;
                s1 += a1 + a3; q1 += a1 * a1 + a3 * a3;
            }
#pragma unroll
            for (int d = 4; d < 32; d <<= 1) {
                v0 = fmaxf(v0, __shfl_xor_sync(0xffffffffu, v0, d));
                v1 = fmaxf(v1, __shfl_xor_sync(0xffffffffu, v1, d));
                s0 += __shfl_xor_sync(0xffffffffu, s0, d);
                q0 += __shfl_xor_sync(0xffffffffu, q0, d);
                s1 += __shfl_xor_sync(0xffffffffu, s1, d);
                q1 += __shfl_xor_sync(0xffffffffu, q1, d);
            }
            if (lane < 4) {
                int co = h * 128 + cog * 64 + n * 8 + (lane << 1);
                out[OUT_XYZ + ((size_t)b * 256 + co) * 1024 + npq] = v0;
                out[OUT_XYZ + ((size_t)b * 256 + co + 1) * 1024 + npq] = v1;
                atomicAdd(&g_sum[192 + co], s0);
                atomicAdd(&g_sum[192 + co + 1], s1);
                atomicAdd(&g_sq[192 + co], q0);
                atomicAdd(&g_sq[192 + co + 1], q1);
            }
        }
    }
}

/* inline fold2 + BN2+ReLU in place + xyz gather */
__global__ void k_fx(const float* __restrict__ xyz, const int* __restrict__ smp,
                     const float* __restrict__ gamma, const float* __restrict__ beta,
                     float* __restrict__ out) {
    int i = blockIdx.x * 256 + threadIdx.x;
    const int total = NB * 256 * NPQ;
    if (i < total) {
        int co = (i >> 10) & 255;
        const float inv = 1.0f / (float)PXT;
        float mu = g_sum[192 + co] * inv;
        float var = g_sq[192 + co] * inv - mu * mu;
        float a = gamma[co] * rsqrtf(var + EPSB);
        float c = beta[co] - a * mu;
        float v = out[OUT_XYZ + i];
        out[OUT_XYZ + i] = fmaxf(fmaf(a, v, c), 0.f);
    } else {
        int j = i - total;
        if (j < NB * NPQ) {
            int b = j >> 10;
            const float* s = xyz + (size_t)(b * NPTS + smp[j]) * 3;
            out[j * 3 + 0] = s[0];
            out[j * 3 + 1] = s[1];
            out[j * 3 + 2] = s[2];
        }
    }
}

extern "C" void kernel_launch(void* const* d_in, const int* in_sizes, int n_in,
                              void* d_out, int out_size) {
    const float* xyz = (const float*)d_in[0];
    const float* pts = (const float*)d_in[1];
    const int*   smp = (const int*)d_in[2];
    const int*   nbr = (const int*)d_in[3];
    const float* W0  = (const float*)d_in[4];
    const float* g0  = (const float*)d_in[6];
    const float* be0 = (const float*)d_in[7];
    const float* W1  = (const float*)d_in[8];
    const float* g1  = (const float*)d_in[10];
    const float* be1 = (const float*)d_in[11];
    const float* W2  = (const float*)d_in[12];
    const float* g2  = (const float*)d_in[14];
    const float* be2 = (const float*)d_in[15];
    float* out = (float*)d_out;

    const int SM1 = 56576;
    cudaFuncSetAttribute(k_g1, cudaFuncAttributeMaxDynamicSharedMemorySize, SM1);
    cudaFuncSetAttribute(k_g2, cudaFuncAttributeMaxDynamicSharedMemorySize, SM2);

    k_prep<<<128, 256>>>(W1, W2);
    k_pf<<<256, 256>>>(pts, W0);
    k_g0s<<<PXT / 128, 256>>>(xyz, W0, smp, nbr);
    k_g1<<<PXT / 128, 256, SM1>>>(g0, be0, W0, xyz, smp, nbr);
    k_g2<<<PXT / 128, 256, SM2>>>(g1, be1, out);
    k_fx<<<(NB * 256 * NPQ + NB * NPQ) / 256, 256>>>(xyz, smp, g2, be2, out);
}